// round 1
// baseline (speedup 1.0000x reference)
#include <cuda_runtime.h>
#include <math.h>

// Problem dims
#define T_SEQ 8192
#define NIN   1024
#define NHID  1024
#define NROWS 3072   // 3*NHID

// ---------------- device scratch (no cudaMalloc allowed) ----------------
__device__ float    g_xproj[(size_t)T_SEQ * NROWS];  // 96 MB: xs@w_ih.T + b
__device__ float    g_h[2][NHID];                    // double-buffered hidden state
__device__ unsigned g_count;                          // barrier arrival counter (monotonic)
__device__ unsigned g_phase;                          // barrier release phase (monotonic)

// ---------------- init: reset state every launch (graph replays) --------
__global__ void init_kernel() {
    int i = blockIdx.x * blockDim.x + threadIdx.x;
    if (i < 2 * NHID) ((float*)g_h)[i] = 0.0f;
    if (i == 0) { g_count = 0u; g_phase = 0u; }
}

// ---------------- GEMM: g_xproj[t, r] = sum_k xs[t,k]*w_ih[r,k] + b[r] --
#define BM 128
#define BN 64
#define BK 16

__global__ void __launch_bounds__(256) xproj_gemm(
    const float* __restrict__ A,     // xs  [T_SEQ, NIN] row-major
    const float* __restrict__ B,     // w_ih [NROWS, NIN] row-major
    const float* __restrict__ bias)  // b [NROWS]
{
    __shared__ float As[BK][BM + 4];
    __shared__ float Bs[BK][BN + 4];

    const int tid = threadIdx.x;
    const int t0 = blockIdx.y * BM;
    const int r0 = blockIdx.x * BN;
    const int ty = tid >> 4;        // 0..15
    const int tx = tid & 15;        // 0..15
    const int m0 = ty * 8;          // 8 rows per thread
    const int n0 = tx * 4;          // 4 cols per thread

    float acc[8][4];
#pragma unroll
    for (int i = 0; i < 8; i++)
#pragma unroll
        for (int j = 0; j < 4; j++) acc[i][j] = 0.0f;

    for (int k0 = 0; k0 < NIN; k0 += BK) {
        // load A tile: 128x16 = 512 float4, 2 per thread
#pragma unroll
        for (int i = 0; i < 2; i++) {
            int idx = tid + 256 * i;
            int row = idx >> 2;
            int c4  = idx & 3;
            float4 v = *(const float4*)(A + (size_t)(t0 + row) * NIN + k0 + 4 * c4);
            As[4 * c4 + 0][row] = v.x;
            As[4 * c4 + 1][row] = v.y;
            As[4 * c4 + 2][row] = v.z;
            As[4 * c4 + 3][row] = v.w;
        }
        // load B tile: 64x16 = 256 float4, 1 per thread
        {
            int row = tid >> 2;
            int c4  = tid & 3;
            float4 v = *(const float4*)(B + (size_t)(r0 + row) * NIN + k0 + 4 * c4);
            Bs[4 * c4 + 0][row] = v.x;
            Bs[4 * c4 + 1][row] = v.y;
            Bs[4 * c4 + 2][row] = v.z;
            Bs[4 * c4 + 3][row] = v.w;
        }
        __syncthreads();

#pragma unroll
        for (int k = 0; k < BK; k++) {
            float4 a0 = *(const float4*)&As[k][m0];
            float4 a1 = *(const float4*)&As[k][m0 + 4];
            float4 bv = *(const float4*)&Bs[k][n0];
            float a[8] = {a0.x, a0.y, a0.z, a0.w, a1.x, a1.y, a1.z, a1.w};
            float bb[4] = {bv.x, bv.y, bv.z, bv.w};
#pragma unroll
            for (int i = 0; i < 8; i++)
#pragma unroll
                for (int j = 0; j < 4; j++)
                    acc[i][j] = fmaf(a[i], bb[j], acc[i][j]);
        }
        __syncthreads();
    }

    float4 bb = *(const float4*)(bias + r0 + n0);
#pragma unroll
    for (int i = 0; i < 8; i++) {
        float4 o;
        o.x = acc[i][0] + bb.x;
        o.y = acc[i][1] + bb.y;
        o.z = acc[i][2] + bb.z;
        o.w = acc[i][3] + bb.w;
        *(float4*)(g_xproj + (size_t)(t0 + m0 + i) * NROWS + r0 + n0) = o;
    }
}

// ---------------- persistent recurrent scan -----------------------------
// 128 CTAs x 256 threads. Each warp owns one hidden unit j:
// rows j, j+NHID, j+2*NHID of w_hh live in registers (96 floats/lane).
// Grid-wide spin barrier with monotonic phase; h broadcast via L2 (ld.cg).
#define NCTA 128
#define HPC  8   // hidden units per CTA (= warps per CTA)

__device__ __forceinline__ unsigned ld_acquire(const unsigned* p) {
    unsigned v;
    asm volatile("ld.acquire.gpu.b32 %0, [%1];" : "=r"(v) : "l"(p) : "memory");
    return v;
}
__device__ __forceinline__ void st_release(unsigned* p, unsigned v) {
    asm volatile("st.release.gpu.b32 [%0], %1;" :: "l"(p), "r"(v) : "memory");
}

__global__ void __launch_bounds__(256, 1) gru_scan_kernel(
    const float* __restrict__ w_hh,  // [NROWS, NHID] row-major
    const float* __restrict__ bn,    // [NHID]
    float* __restrict__ out,         // [2*T_SEQ*NHID] or [T_SEQ*NHID]
    int dup)
{
    const int warp = threadIdx.x >> 5;
    const int lane = threadIdx.x & 31;
    const int j = blockIdx.x * HPC + warp;

    // Register-resident weights: lane owns cols {4*lane..4*lane+3} + 128*k
    float4 wr[8], wz[8], wg[8];
    {
        const float4* pr = (const float4*)(w_hh + (size_t)j * NHID);
        const float4* pz = (const float4*)(w_hh + (size_t)(j + NHID) * NHID);
        const float4* pg = (const float4*)(w_hh + (size_t)(j + 2 * NHID) * NHID);
#pragma unroll
        for (int k = 0; k < 8; k++) {
            int c = lane + 32 * k;
            wr[k] = pr[c];
            wz[k] = pz[c];
            wg[k] = pg[c];
        }
    }
    const float bnj = bn[j];

    for (int t = 0; t < T_SEQ; t++) {
        const float4* hb = (const float4*)g_h[t & 1];
        float ar = 0.0f, az = 0.0f, ag = 0.0f;
#pragma unroll
        for (int k = 0; k < 8; k++) {
            // MUST bypass L1: h is written by other SMs between visits.
            float4 h4 = __ldcg(&hb[lane + 32 * k]);
            ar = fmaf(wr[k].x, h4.x, fmaf(wr[k].y, h4.y, fmaf(wr[k].z, h4.z, fmaf(wr[k].w, h4.w, ar))));
            az = fmaf(wz[k].x, h4.x, fmaf(wz[k].y, h4.y, fmaf(wz[k].z, h4.z, fmaf(wz[k].w, h4.w, az))));
            ag = fmaf(wg[k].x, h4.x, fmaf(wg[k].y, h4.y, fmaf(wg[k].z, h4.z, fmaf(wg[k].w, h4.w, ag))));
        }
#pragma unroll
        for (int o = 16; o > 0; o >>= 1) {
            ar += __shfl_xor_sync(0xffffffffu, ar, o);
            az += __shfl_xor_sync(0xffffffffu, az, o);
            ag += __shfl_xor_sync(0xffffffffu, ag, o);
        }
        if (lane == 0) {
            const float* xp = g_xproj + (size_t)t * NROWS;
            float xr = xp[j];
            float xz = xp[NHID + j];
            float xg = xp[2 * NHID + j];
            float hprev = __ldcg(&((const float*)g_h)[(t & 1) * NHID + j]);
            float r = 1.0f / (1.0f + __expf(-(xr + ar)));
            float z = 1.0f / (1.0f + __expf(-(xz + az)));
            float g = tanhf(xg + r * (ag + bnj));
            float hn = fmaf(z, hprev - g, g);   // (1-z)*g + z*h
            g_h[(t + 1) & 1][j] = hn;
            out[(size_t)t * NHID + j] = hn;
            if (dup) out[(size_t)T_SEQ * NHID + (size_t)t * NHID + j] = hn;
        }

        // grid barrier: monotonic count + monotonic release phase.
        __syncthreads();
        if (threadIdx.x == 0) {
            __threadfence();  // publish this CTA's h writes before arrival
            unsigned target = (unsigned)(t + 1);
            unsigned old = atomicAdd(&g_count, 1u);
            if (old == target * NCTA - 1u) {
                st_release(&g_phase, target);
            } else {
                while (ld_acquire(&g_phase) < target) { }
            }
        }
        __syncthreads();
    }
}

// ---------------- launch ------------------------------------------------
extern "C" void kernel_launch(void* const* d_in, const int* in_sizes, int n_in,
                              void* d_out, int out_size) {
    const float* xs   = (const float*)d_in[0];
    const float* w_ih = (const float*)d_in[1];
    const float* w_hh = (const float*)d_in[2];
    const float* b    = (const float*)d_in[3];
    const float* bn   = (const float*)d_in[4];
    float* out = (float*)d_out;

    init_kernel<<<8, 256>>>();

    dim3 gemm_grid(NROWS / BN, T_SEQ / BM);
    xproj_gemm<<<gemm_grid, 256>>>(xs, w_ih, b);

    int dup = (out_size >= 2 * T_SEQ * NHID) ? 1 : 0;
    gru_scan_kernel<<<NCTA, 256>>>(w_hh, bn, out, dup);
}

// round 4
// speedup vs baseline: 1.3261x; 1.3261x over previous
#include <cuda_runtime.h>
#include <math.h>

// Problem dims
#define T_SEQ 8192
#define NIN   1024
#define NHID  1024
#define NROWS 3072   // 3*NHID

#define NCTA 128
#define HPC  8       // hidden units per CTA (= warps per CTA)

// ---------------- device scratch (no cudaMalloc allowed) ----------------
__device__ float    g_xproj[(size_t)T_SEQ * NROWS];  // 96 MB: xs@w_ih.T + b
__device__ float    g_h[2][NHID];                    // double-buffered hidden state
__device__ unsigned g_count;                          // barrier arrival counter (monotonic)
__device__ unsigned g_phase;                          // barrier release phase (monotonic)

// ---------------- init: reset state every launch (graph replays) --------
__global__ void init_kernel() {
    int i = blockIdx.x * blockDim.x + threadIdx.x;
    if (i < 2 * NHID) ((float*)g_h)[i] = 0.0f;
    if (i == 0) { g_count = 0u; g_phase = 0u; }
}

// ---------------- GEMM: g_xproj[t, r] = sum_k xs[t,k]*w_ih[r,k] + b[r] --
#define BM 128
#define BN 64
#define BK 16

__global__ void __launch_bounds__(256) xproj_gemm(
    const float* __restrict__ A,     // xs  [T_SEQ, NIN] row-major
    const float* __restrict__ B,     // w_ih [NROWS, NIN] row-major
    const float* __restrict__ bias)  // b [NROWS]
{
    __shared__ float As[BK][BM + 4];
    __shared__ float Bs[BK][BN + 4];

    const int tid = threadIdx.x;
    const int t0 = blockIdx.y * BM;
    const int r0 = blockIdx.x * BN;
    const int ty = tid >> 4;        // 0..15
    const int tx = tid & 15;        // 0..15
    const int m0 = ty * 8;          // 8 rows per thread
    const int n0 = tx * 4;          // 4 cols per thread

    float acc[8][4];
#pragma unroll
    for (int i = 0; i < 8; i++)
#pragma unroll
        for (int j = 0; j < 4; j++) acc[i][j] = 0.0f;

    for (int k0 = 0; k0 < NIN; k0 += BK) {
#pragma unroll
        for (int i = 0; i < 2; i++) {
            int idx = tid + 256 * i;
            int row = idx >> 2;
            int c4  = idx & 3;
            float4 v = *(const float4*)(A + (size_t)(t0 + row) * NIN + k0 + 4 * c4);
            As[4 * c4 + 0][row] = v.x;
            As[4 * c4 + 1][row] = v.y;
            As[4 * c4 + 2][row] = v.z;
            As[4 * c4 + 3][row] = v.w;
        }
        {
            int row = tid >> 2;
            int c4  = tid & 3;
            float4 v = *(const float4*)(B + (size_t)(r0 + row) * NIN + k0 + 4 * c4);
            Bs[4 * c4 + 0][row] = v.x;
            Bs[4 * c4 + 1][row] = v.y;
            Bs[4 * c4 + 2][row] = v.z;
            Bs[4 * c4 + 3][row] = v.w;
        }
        __syncthreads();

#pragma unroll
        for (int k = 0; k < BK; k++) {
            float4 a0 = *(const float4*)&As[k][m0];
            float4 a1 = *(const float4*)&As[k][m0 + 4];
            float4 bv = *(const float4*)&Bs[k][n0];
            float a[8] = {a0.x, a0.y, a0.z, a0.w, a1.x, a1.y, a1.z, a1.w};
            float bb[4] = {bv.x, bv.y, bv.z, bv.w};
#pragma unroll
            for (int i = 0; i < 8; i++)
#pragma unroll
                for (int j = 0; j < 4; j++)
                    acc[i][j] = fmaf(a[i], bb[j], acc[i][j]);
        }
        __syncthreads();
    }

    float4 bb = *(const float4*)(bias + r0 + n0);
#pragma unroll
    for (int i = 0; i < 8; i++) {
        float4 o;
        o.x = acc[i][0] + bb.x;
        o.y = acc[i][1] + bb.y;
        o.z = acc[i][2] + bb.z;
        o.w = acc[i][3] + bb.w;
        *(float4*)(g_xproj + (size_t)(t0 + m0 + i) * NROWS + r0 + n0) = o;
    }
}

// ---------------- persistent recurrent scan -----------------------------
__device__ __forceinline__ unsigned ld_acquire(const unsigned* p) {
    unsigned v;
    asm volatile("ld.acquire.gpu.b32 %0, [%1];" : "=r"(v) : "l"(p) : "memory");
    return v;
}
__device__ __forceinline__ void st_release(unsigned* p, unsigned v) {
    asm volatile("st.release.gpu.b32 [%0], %1;" :: "l"(p), "r"(v) : "memory");
}
__device__ __forceinline__ float fsigmoid(float x) {
    float e = __expf(-x);
    return __fdividef(1.0f, 1.0f + e);
}
__device__ __forceinline__ float ftanh(float x) {
    float e2 = __expf(2.0f * x);
    return 1.0f - __fdividef(2.0f, e2 + 1.0f);
}

__global__ void __launch_bounds__(256, 1) gru_scan_kernel(
    const float* __restrict__ w_hh,  // [NROWS, NHID] row-major
    const float* __restrict__ bn,    // [NHID]
    float* __restrict__ out,         // ys duplicated at offset T*NHID if dup
    int dup)
{
    __shared__ float4 hs4[NHID / 4];   // staged hidden state (full h, 4 KB)

    const int tid  = threadIdx.x;
    const int warp = tid >> 5;
    const int lane = tid & 31;
    const int j = blockIdx.x * HPC + warp;

    // Register-resident weights: lane owns float4 cols {lane+32k}, k=0..7
    float4 wr[8], wz[8], wg[8];
    {
        const float4* pr = (const float4*)(w_hh + (size_t)j * NHID);
        const float4* pz = (const float4*)(w_hh + (size_t)(j + NHID) * NHID);
        const float4* pg = (const float4*)(w_hh + (size_t)(j + 2 * NHID) * NHID);
#pragma unroll
        for (int k = 0; k < 8; k++) {
            int c = lane + 32 * k;
            wr[k] = pr[c];
            wz[k] = pz[c];
            wg[k] = pg[c];
        }
    }
    const float bnj = bn[j];

    // Prefetch x_proj for t=0 (lane0 only holds the values)
    float cxr = 0.f, cxz = 0.f, cxg = 0.f;   // current step
    float nxr = 0.f, nxz = 0.f, nxg = 0.f;   // next step
    if (lane == 0) {
        const float* xp = g_xproj;
        cxr = __ldcs(xp + j);
        cxz = __ldcs(xp + NHID + j);
        cxg = __ldcs(xp + 2 * NHID + j);
    }

    for (int t = 0; t < T_SEQ; t++) {
        // ---- stage h into shared memory (one pass, bypassing L1) ----
        {
            const float4* hb = (const float4*)g_h[t & 1];
            hs4[tid] = __ldcg(&hb[tid]);
        }
        __syncthreads();

        // ---- prefetch x_proj for t+1 (overlaps dot + barrier) ----
        if (lane == 0 && t + 1 < T_SEQ) {
            const float* xp = g_xproj + (size_t)(t + 1) * NROWS;
            nxr = __ldcs(xp + j);
            nxz = __ldcs(xp + NHID + j);
            nxg = __ldcs(xp + 2 * NHID + j);
        }

        // ---- dot products from shared memory ----
        float ar = 0.0f, az = 0.0f, ag = 0.0f;
#pragma unroll
        for (int k = 0; k < 8; k++) {
            float4 h4 = hs4[lane + 32 * k];
            ar = fmaf(wr[k].x, h4.x, fmaf(wr[k].y, h4.y, fmaf(wr[k].z, h4.z, fmaf(wr[k].w, h4.w, ar))));
            az = fmaf(wz[k].x, h4.x, fmaf(wz[k].y, h4.y, fmaf(wz[k].z, h4.z, fmaf(wz[k].w, h4.w, az))));
            ag = fmaf(wg[k].x, h4.x, fmaf(wg[k].y, h4.y, fmaf(wg[k].z, h4.z, fmaf(wg[k].w, h4.w, ag))));
        }
#pragma unroll
        for (int o = 16; o > 0; o >>= 1) {
            ar += __shfl_xor_sync(0xffffffffu, ar, o);
            az += __shfl_xor_sync(0xffffffffu, az, o);
            ag += __shfl_xor_sync(0xffffffffu, ag, o);
        }

        float hn = 0.0f;
        if (lane == 0) {
            float hprev = ((const float*)hs4)[j];
            float r = fsigmoid(cxr + ar);
            float z = fsigmoid(cxz + az);
            float g = ftanh(cxg + r * (ag + bnj));
            hn = fmaf(z, hprev - g, g);              // (1-z)*g + z*h
            __stcg(&g_h[(t + 1) & 1][j], hn);
        }

        // ---- grid barrier: PROVEN R1 protocol (atomic count + phase) ----
        __syncthreads();
        if (tid == 0) {
            __threadfence();  // publish this CTA's h writes before arrival
            unsigned target = (unsigned)(t + 1);
            unsigned old = atomicAdd(&g_count, 1u);
            if (old == target * NCTA - 1u) {
                st_release(&g_phase, target);
            } else {
                while (ld_acquire(&g_phase) < target) { }
            }
        }
        __syncthreads();

        // ---- off-critical-path work: output stores, rotate prefetch ----
        if (lane == 0) {
            __stcs(out + (size_t)t * NHID + j, hn);
            if (dup) __stcs(out + (size_t)T_SEQ * NHID + (size_t)t * NHID + j, hn);
            cxr = nxr; cxz = nxz; cxg = nxg;
        }
    }
}

// ---------------- launch ------------------------------------------------
extern "C" void kernel_launch(void* const* d_in, const int* in_sizes, int n_in,
                              void* d_out, int out_size) {
    const float* xs   = (const float*)d_in[0];
    const float* w_ih = (const float*)d_in[1];
    const float* w_hh = (const float*)d_in[2];
    const float* b    = (const float*)d_in[3];
    const float* bn   = (const float*)d_in[4];
    float* out = (float*)d_out;

    init_kernel<<<8, 256>>>();

    dim3 gemm_grid(NROWS / BN, T_SEQ / BM);
    xproj_gemm<<<gemm_grid, 256>>>(xs, w_ih, b);

    int dup = (out_size >= 2 * T_SEQ * NHID) ? 1 : 0;
    gru_scan_kernel<<<NCTA, 256>>>(w_hh, bn, out, dup);
}